// round 13
// baseline (speedup 1.0000x reference)
#include <cuda_runtime.h>
#include <cuda_fp16.h>
#include <cstdint>

#define T_TOTAL 9792
#define EMBED   1024
#define NHEADS  16
#define HDIM    64
#define MTILES  77          // ceil(9792/128)

// ------------------------- scratch (static device) -------------------------
__device__ __half g_ahi[(size_t)T_TOTAL * EMBED];
__device__ __half g_alo[(size_t)T_TOTAL * EMBED];
__device__ __half g_chi[(size_t)T_TOTAL * EMBED];
__device__ __half g_whi[4][(size_t)EMBED * EMBED];

__device__ __half g_qhi[(size_t)T_TOTAL * EMBED];  // rope'd q * 0.125, hi
__device__ __half g_qlo[(size_t)T_TOTAL * EMBED];  // rope'd q * 0.125, lo
__device__ __half g_kh [(size_t)T_TOTAL * EMBED];  // rope'd k, fp16
__device__ __half g_vh [(size_t)T_TOTAL * EMBED];  // v, fp16

__constant__ int c_cu[12] = {0, 1024, 1792, 2688, 3200, 4224, 4864, 5888, 6656, 7168, 8064, 9088};
__constant__ int c_nt[12] = {16, 12, 14, 8, 16, 10, 16, 12, 8, 14, 16, 11};

// ------------------------- PTX helpers (baseline ISA only) ------------------
__device__ __forceinline__ uint32_t smem_u32(const void* p) {
    uint32_t a;
    asm("{ .reg .u64 t; cvta.to.shared.u64 t, %1; cvt.u32.u64 %0, t; }" : "=r"(a) : "l"(p));
    return a;
}

#define LDSM_X4(R, addr)                                                      \
    asm volatile("ldmatrix.sync.aligned.m8n8.x4.shared.b16 {%0,%1,%2,%3}, [%4];" \
        : "=r"((R)[0]), "=r"((R)[1]), "=r"((R)[2]), "=r"((R)[3]) : "r"(addr))

#define LDSM_X4_T(R, addr)                                                    \
    asm volatile("ldmatrix.sync.aligned.m8n8.x4.trans.shared.b16 {%0,%1,%2,%3}, [%4];" \
        : "=r"((R)[0]), "=r"((R)[1]), "=r"((R)[2]), "=r"((R)[3]) : "r"(addr))

#define MMA_F16(C, A, B0, B1)                                                 \
    asm volatile("mma.sync.aligned.m16n8k16.row.col.f32.f16.f16.f32 "         \
        "{%0,%1,%2,%3}, {%4,%5,%6,%7}, {%8,%9}, {%0,%1,%2,%3};"               \
        : "+f"((C)[0]), "+f"((C)[1]), "+f"((C)[2]), "+f"((C)[3])              \
        : "r"((A)[0]), "r"((A)[1]), "r"((A)[2]), "r"((A)[3]), "r"(B0), "r"(B1))

__device__ __forceinline__ void cp16(uint32_t dst, const void* src, int srcbytes) {
    asm volatile("cp.async.cg.shared.global [%0], [%1], 16, %2;"
                 :: "r"(dst), "l"(src), "r"(srcbytes) : "memory");
}
#define CP_COMMIT() asm volatile("cp.async.commit_group;" ::: "memory")
#define CP_WAIT(N)  asm volatile("cp.async.wait_group %0;" :: "n"(N) : "memory")

__device__ __forceinline__ uint32_t pack_h2(__half a, __half b) {
    __half2 t = __halves2half2(a, b);
    return *(uint32_t*)&t;
}

// ------------------------- prep: splits + weight converts -------------------
__global__ void prep_kernel(const float* __restrict__ hidden,
                            const float* __restrict__ w0, const float* __restrict__ w1,
                            const float* __restrict__ w2, const float* __restrict__ w3) {
    int z = blockIdx.z;
    int i = blockIdx.x * blockDim.x + threadIdx.x;
    if (z == 0) {
        int n4 = T_TOTAL * EMBED / 4;
        if (i >= n4) return;
        float4 v = ((const float4*)hidden)[i];
        union { __half b[4]; uint2 u; } H, L;
        float x[4] = {v.x, v.y, v.z, v.w};
#pragma unroll
        for (int j = 0; j < 4; j++) {
            __half h = __float2half(x[j]);
            H.b[j] = h;
            L.b[j] = __float2half(x[j] - __half2float(h));
        }
        ((uint2*)g_ahi)[i] = H.u;
        ((uint2*)g_alo)[i] = L.u;
    } else {
        int n4 = EMBED * EMBED / 4;
        if (i >= n4) return;
        const float* src = (z == 1) ? w0 : (z == 2) ? w1 : (z == 3) ? w2 : w3;
        float4 v = ((const float4*)src)[i];
        union { __half b[4]; uint2 u; } H;
        H.b[0] = __float2half(v.x);
        H.b[1] = __float2half(v.y);
        H.b[2] = __float2half(v.z);
        H.b[3] = __float2half(v.w);
        ((uint2*)g_whi[z - 1])[i] = H.u;
    }
}

// ------------------------- GEMM mainloop (1-pass, 3-stage) ------------------
#define SM_GEMM_TOTAL 98304   // 3 x 32K stages

__device__ __forceinline__ uint32_t sw_off(int r, int chunk) {
    uint32_t off = (uint32_t)(r * 128 + chunk * 16);
    return off ^ ((off >> 3) & 0x70);
}

__device__ __forceinline__ void gemm_mainloop(
    const __half* __restrict__ Ahi, const __half* __restrict__ Bhi,
    int M, float (&acc)[4][4][4], char* smem)
{
    constexpr uint32_t OFF_BHI  = 16384;
    constexpr uint32_t SM_STAGE = 32768;
    constexpr int NS = 3;

    const uint32_t sb = smem_u32(smem);
    const int tid = threadIdx.x;
    const int wid = tid >> 5, lane = tid & 31;
    const int row0 = blockIdx.y * 128;
    const int col0 = blockIdx.x * 128;
    const int wm = (wid & 1) * 64;
    const int wn = (wid >> 1) * 32;

#pragma unroll
    for (int a = 0; a < 4; a++)
#pragma unroll
        for (int b = 0; b < 4; b++)
#pragma unroll
            for (int c = 0; c < 4; c++) acc[a][b][c] = 0.0f;

    const int l_r[4] = { (tid + 0) >> 3, (tid + 256) >> 3, (tid + 512) >> 3, (tid + 768) >> 3 };
    const int l_c = tid & 7;

    const int a_r = lane & 15;
    const int a_c = lane >> 4;
    const int b_r = ((lane >> 4) << 3) + (lane & 7);
    const int b_c = (lane >> 3) & 1;

    auto load_tile = [&](int kt, int stage) {
        const int k0 = kt * 64;
        const uint32_t stb = sb + stage * SM_STAGE;
#pragma unroll
        for (int j = 0; j < 4; j++) {
            int r = l_r[j];
            uint32_t sw = sw_off(r, l_c);
            int apred = (row0 + r < M) ? 16 : 0;
            size_t aoff = (size_t)(row0 + r) * EMBED + k0 + l_c * 8;
            size_t boff = (size_t)(col0 + r) * EMBED + k0 + l_c * 8;
            cp16(stb + sw, Ahi + aoff, apred);
            cp16(stb + OFF_BHI + sw, Bhi + boff, 16);
        }
        CP_COMMIT();
    };

#pragma unroll
    for (int s = 0; s < NS - 1; s++) load_tile(s, s);

    for (int kt = 0; kt < 16; kt++) {
        CP_WAIT(NS - 2);        // tile kt complete
        __syncthreads();        // visibility + all warps done with recycled slot
        if (kt + NS - 1 < 16) load_tile(kt + NS - 1, (kt + NS - 1) % NS);
        else CP_COMMIT();       // keep wait-count invariant

        const uint32_t stb = sb + (kt % NS) * SM_STAGE;
#pragma unroll
        for (int ks = 0; ks < 4; ks++) {
            uint32_t ahi[4][4];
#pragma unroll
            for (int mt = 0; mt < 4; mt++) {
                uint32_t sw = sw_off(wm + mt * 16 + a_r, ks * 2 + a_c);
                LDSM_X4(ahi[mt], stb + sw);
            }
            uint32_t bhi[2][4];
#pragma unroll
            for (int np = 0; np < 2; np++) {
                uint32_t sw = sw_off(wn + np * 16 + b_r, ks * 2 + b_c);
                LDSM_X4(bhi[np], stb + OFF_BHI + sw);
            }
#pragma unroll
            for (int mt = 0; mt < 4; mt++) {
#pragma unroll
                for (int nt = 0; nt < 4; nt++) {
                    uint32_t bh0 = bhi[nt >> 1][(nt & 1) * 2];
                    uint32_t bh1 = bhi[nt >> 1][(nt & 1) * 2 + 1];
                    MMA_F16(acc[mt][nt], ahi[mt], bh0, bh1);
                }
            }
        }
    }
}

// ------------------------- QKV GEMM (1-pass) + fused rope epilogue ----------
__global__ __launch_bounds__(256, 2) void qkv_mma_kernel(
    const float* __restrict__ qb, const float* __restrict__ vb,
    const float* __restrict__ cosp, const float* __restrict__ sinp)
{
    extern __shared__ char smem[];
    const int z = blockIdx.z;
    float acc[4][4][4];
    gemm_mainloop(g_ahi, g_whi[z], T_TOTAL, acc, smem);

    const int tid = threadIdx.x;
    const int wid = tid >> 5, lane = tid & 31;
    const int row0 = blockIdx.y * 128;
    const int col0 = blockIdx.x * 128;
    const int wm = (wid & 1) * 64;
    const int wn = (wid >> 1) * 32;
    const int erow = lane >> 2;
    const int ecol = (lane & 3) * 2;

    if (z == 2) {
#pragma unroll
        for (int mt = 0; mt < 4; mt++) {
            int r0g = row0 + wm + mt * 16 + erow;
#pragma unroll
            for (int nt = 0; nt < 4; nt++) {
                int colg = col0 + wn + nt * 8 + ecol;
                float b0 = vb[colg], b1 = vb[colg + 1];
                if (r0g < T_TOTAL) {
                    __half2 v = __floats2half2_rn(acc[mt][nt][0] + b0, acc[mt][nt][1] + b1);
                    *(__half2*)&g_vh[(size_t)r0g * EMBED + colg] = v;
                }
                if (r0g + 8 < T_TOTAL) {
                    __half2 v = __floats2half2_rn(acc[mt][nt][2] + b0, acc[mt][nt][3] + b1);
                    *(__half2*)&g_vh[(size_t)(r0g + 8) * EMBED + colg] = v;
                }
            }
        }
        return;
    }

    // q/k: stage fp32 tile in smem, then rope across the (d, d+32) pairs
    __syncthreads();
    float* st = (float*)smem;              // [128][130]
#pragma unroll
    for (int mt = 0; mt < 4; mt++) {
        int r0 = wm + mt * 16 + erow;
#pragma unroll
        for (int nt = 0; nt < 4; nt++) {
            int c = wn + nt * 8 + ecol;
            float b0 = (z == 0) ? qb[col0 + c] : 0.0f;
            float b1 = (z == 0) ? qb[col0 + c + 1] : 0.0f;
            st[r0 * 130 + c]           = acc[mt][nt][0] + b0;
            st[r0 * 130 + c + 1]       = acc[mt][nt][1] + b1;
            st[(r0 + 8) * 130 + c]     = acc[mt][nt][2] + b0;
            st[(r0 + 8) * 130 + c + 1] = acc[mt][nt][3] + b1;
        }
    }
    __syncthreads();

    for (int i = tid; i < 128 * 64; i += 256) {
        int r = i >> 6;
        int p = i & 63;
        int t = row0 + r;
        if (t >= T_TOTAL) continue;
        int hh = p >> 5, d = p & 31;
        int c1 = hh * 64 + d, c2 = c1 + 32;
        float x1 = st[r * 130 + c1], x2 = st[r * 130 + c2];
        float cc = cosp[t * HDIM + d], ss = sinp[t * HDIM + d];
        float y1 = x1 * cc - x2 * ss;
        float y2 = x2 * cc + x1 * ss;
        size_t o1 = (size_t)t * EMBED + col0 + c1;
        size_t o2 = o1 + 32;
        if (z == 0) {
            y1 *= 0.125f; y2 *= 0.125f;
            __half h1 = __float2half(y1), h2 = __float2half(y2);
            g_qhi[o1] = h1;
            g_qhi[o2] = h2;
            g_qlo[o1] = __float2half(y1 - __half2float(h1));
            g_qlo[o2] = __float2half(y2 - __half2float(h2));
        } else {
            g_kh[o1] = __float2half(y1);
            g_kh[o2] = __float2half(y2);
        }
    }
}

// ------------------------- output projection (1-pass, 3-stage) --------------
__global__ __launch_bounds__(256, 2) void out_mma_kernel(const float* __restrict__ ob,
                                                         float* __restrict__ out)
{
    extern __shared__ char smem[];
    float acc[4][4][4];
    gemm_mainloop(g_chi, g_whi[3], T_TOTAL, acc, smem);

    const int tid = threadIdx.x;
    const int wid = tid >> 5, lane = tid & 31;
    const int row0 = blockIdx.y * 128;
    const int col0 = blockIdx.x * 128;
    const int wm = (wid & 1) * 64;
    const int wn = (wid >> 1) * 32;
    const int erow = lane >> 2;
    const int ecol = (lane & 3) * 2;
#pragma unroll
    for (int mt = 0; mt < 4; mt++) {
        int r0g = row0 + wm + mt * 16 + erow;
#pragma unroll
        for (int nt = 0; nt < 4; nt++) {
            int colg = col0 + wn + nt * 8 + ecol;
            float b0 = ob[colg], b1 = ob[colg + 1];
            if (r0g < T_TOTAL) {
                float2 v = make_float2(acc[mt][nt][0] + b0, acc[mt][nt][1] + b1);
                *(float2*)&out[(size_t)r0g * EMBED + colg] = v;
            }
            if (r0g + 8 < T_TOTAL) {
                float2 v = make_float2(acc[mt][nt][2] + b0, acc[mt][nt][3] + b1);
                *(float2*)&out[(size_t)(r0g + 8) * EMBED + colg] = v;
            }
        }
    }
}

// ------------------------- flash attention (fp16 MMA) ----------------------
// S = (Qhi+Qlo)·K (2-pass), O = P·V (1-pass). 3-stage KV pipeline.
#define FSM_QHI 0
#define FSM_QLO 8192
#define FSM_KV  16384
#define FSM_TOTAL 65536

__global__ __launch_bounds__(128) void flash_kernel() {
    extern __shared__ char smem[];
    const uint32_t sb = smem_u32(smem);
    const int tid = threadIdx.x;
    const int wid = tid >> 5, lane = tid & 31;
    const int h = blockIdx.y;

    int rem = blockIdx.x, b = 0;
    while (rem >= c_nt[b]) { rem -= c_nt[b]; ++b; }
    const int qt = rem;
    const int tok0 = c_cu[b];
    const int tokq = tok0 + qt * 64;

    auto kvload = [&](int kt, int slot) {
        const int tokk = tok0 + kt * 64;
        const uint32_t kb = sb + FSM_KV + slot * 16384;
#pragma unroll
        for (int j = 0; j < 4; j++) {
            int idx = tid + j * 128;
            int r = idx >> 3;
            int c = idx & 7;
            uint32_t sw = sw_off(r, c);
            size_t go = (size_t)(tokk + r) * EMBED + h * HDIM + c * 8;
            cp16(kb + sw, g_kh + go, 16);
            cp16(kb + 8192 + sw, g_vh + go, 16);
        }
    };

#pragma unroll
    for (int j = 0; j < 4; j++) {
        int idx = tid + j * 128;
        int r = idx >> 3;
        int c = idx & 7;
        uint32_t sw = sw_off(r, c);
        size_t go = (size_t)(tokq + r) * EMBED + h * HDIM + c * 8;
        cp16(sb + FSM_QHI + sw, g_qhi + go, 16);
        cp16(sb + FSM_QLO + sw, g_qlo + go, 16);
    }
    kvload(0, 0);
    CP_COMMIT();
    if (qt >= 1) kvload(1, 1);
    CP_COMMIT();

    CP_WAIT(1);
    __syncthreads();

    uint32_t qhi[4][4], qlo[4][4];
    {
        const int a_row = wid * 16 + (lane & 15);
        const int a_c = lane >> 4;
#pragma unroll
        for (int ks = 0; ks < 4; ks++) {
            uint32_t sw = sw_off(a_row, ks * 2 + a_c);
            LDSM_X4(qhi[ks], sb + FSM_QHI + sw);
            LDSM_X4(qlo[ks], sb + FSM_QLO + sw);
        }
    }

    float oacc[8][4];
#pragma unroll
    for (int n = 0; n < 8; n++)
#pragma unroll
        for (int c = 0; c < 4; c++) oacc[n][c] = 0.0f;
    float m0 = -1e30f, m1 = -1e30f, l0 = 0.0f, l1 = 0.0f;

    const int b_r = ((lane >> 4) << 3) + (lane & 7);
    const int b_c = (lane >> 3) & 1;
    const int v_row = ((lane >> 3) & 1) * 8 + (lane & 7);
    const int v_ch  = lane >> 4;

    for (int kt = 0; kt <= qt; kt++) {
        CP_WAIT(1);
        __syncthreads();
        if (kt + 2 <= qt) kvload(kt + 2, (kt + 2) % 3);
        CP_COMMIT();

        const uint32_t kbase = sb + FSM_KV + (kt % 3) * 16384;
        const uint32_t vbase = kbase + 8192;

        float sacc[8][4];
#pragma unroll
        for (int n = 0; n < 8; n++)
#pragma unroll
            for (int c = 0; c < 4; c++) sacc[n][c] = 0.0f;

#pragma unroll
        for (int ks = 0; ks < 4; ks++) {
            uint32_t kf[4][4];
#pragma unroll
            for (int np = 0; np < 4; np++) {
                uint32_t sw = sw_off(np * 16 + b_r, ks * 2 + b_c);
                LDSM_X4(kf[np], kbase + sw);
            }
#pragma unroll
            for (int nt = 0; nt < 8; nt++) {
                uint32_t b0 = kf[nt >> 1][(nt & 1) * 2];
                uint32_t b1 = kf[nt >> 1][(nt & 1) * 2 + 1];
                MMA_F16(sacc[nt], qhi[ks], b0, b1);
                MMA_F16(sacc[nt], qlo[ks], b0, b1);
            }
        }

        if (kt == qt) {
            const int r0 = wid * 16 + (lane >> 2);
#pragma unroll
            for (int nt = 0; nt < 8; nt++) {
                int c0 = nt * 8 + (lane & 3) * 2;
                if (c0 > r0) sacc[nt][0] = -1e30f;
                if (c0 + 1 > r0) sacc[nt][1] = -1e30f;
                if (c0 > r0 + 8) sacc[nt][2] = -1e30f;
                if (c0 + 1 > r0 + 8) sacc[nt][3] = -1e30f;
            }
        }

        {
            float tm0 = -1e30f, tm1 = -1e30f;
#pragma unroll
            for (int nt = 0; nt < 8; nt++) {
                tm0 = fmaxf(tm0, fmaxf(sacc[nt][0], sacc[nt][1]));
                tm1 = fmaxf(tm1, fmaxf(sacc[nt][2], sacc[nt][3]));
            }
            tm0 = fmaxf(tm0, __shfl_xor_sync(0xffffffffu, tm0, 1, 32));
            tm0 = fmaxf(tm0, __shfl_xor_sync(0xffffffffu, tm0, 2, 32));
            tm1 = fmaxf(tm1, __shfl_xor_sync(0xffffffffu, tm1, 1, 32));
            tm1 = fmaxf(tm1, __shfl_xor_sync(0xffffffffu, tm1, 2, 32));
            float mn0 = fmaxf(m0, tm0), mn1 = fmaxf(m1, tm1);
            float al0 = __expf(m0 - mn0), al1 = __expf(m1 - mn1);
            float rs0 = 0.0f, rs1 = 0.0f;
#pragma unroll
            for (int nt = 0; nt < 8; nt++) {
                sacc[nt][0] = __expf(sacc[nt][0] - mn0); rs0 += sacc[nt][0];
                sacc[nt][1] = __expf(sacc[nt][1] - mn0); rs0 += sacc[nt][1];
                sacc[nt][2] = __expf(sacc[nt][2] - mn1); rs1 += sacc[nt][2];
                sacc[nt][3] = __expf(sacc[nt][3] - mn1); rs1 += sacc[nt][3];
            }
            rs0 += __shfl_xor_sync(0xffffffffu, rs0, 1, 32);
            rs0 += __shfl_xor_sync(0xffffffffu, rs0, 2, 32);
            rs1 += __shfl_xor_sync(0xffffffffu, rs1, 1, 32);
            rs1 += __shfl_xor_sync(0xffffffffu, rs1, 2, 32);
            l0 = l0 * al0 + rs0; m0 = mn0;
            l1 = l1 * al1 + rs1; m1 = mn1;
#pragma unroll
            for (int n = 0; n < 8; n++) {
                oacc[n][0] *= al0; oacc[n][1] *= al0;
                oacc[n][2] *= al1; oacc[n][3] *= al1;
            }
        }

        // O += P @ V (1-pass fp16 P)
#pragma unroll
        for (int ks = 0; ks < 4; ks++) {
            uint32_t ph[4];
            {
                float* s0 = sacc[2 * ks];
                float* s1 = sacc[2 * ks + 1];
                ph[0] = pack_h2(__float2half(s0[0]), __float2half(s0[1]));
                ph[1] = pack_h2(__float2half(s0[2]), __float2half(s0[3]));
                ph[2] = pack_h2(__float2half(s1[0]), __float2half(s1[1]));
                ph[3] = pack_h2(__float2half(s1[2]), __float2half(s1[3]));
            }
#pragma unroll
            for (int nd2 = 0; nd2 < 4; nd2++) {
                uint32_t vf[4];
                uint32_t sw = sw_off(ks * 16 + v_row, nd2 * 2 + v_ch);
                LDSM_X4_T(vf, vbase + sw);
                MMA_F16(oacc[nd2 * 2],     ph, vf[0], vf[1]);
                MMA_F16(oacc[nd2 * 2 + 1], ph, vf[2], vf[3]);
            }
        }
    }

    // Epilogue: normalize + write fp16 (out GEMM is 1-pass now)
    {
        float inv0 = 1.0f / l0;
        float inv1 = 1.0f / l1;
        int gr0 = tokq + wid * 16 + (lane >> 2);
        int gr1 = gr0 + 8;
#pragma unroll
        for (int nt = 0; nt < 8; nt++) {
            int col = h * HDIM + nt * 8 + (lane & 3) * 2;
            *(__half2*)&g_chi[(size_t)gr0 * EMBED + col] =
                __floats2half2_rn(oacc[nt][0] * inv0, oacc[nt][1] * inv0);
            *(__half2*)&g_chi[(size_t)gr1 * EMBED + col] =
                __floats2half2_rn(oacc[nt][2] * inv1, oacc[nt][3] * inv1);
        }
    }
}

// ---------------------------------------------------------------------------
extern "C" void kernel_launch(void* const* d_in, const int* in_sizes, int n_in,
                              void* d_out, int out_size)
{
    const float* hidden = (const float*)d_in[0];
    const float* cosp   = (const float*)d_in[1];
    const float* sinp   = (const float*)d_in[2];
    const float* q_w    = (const float*)d_in[3];
    const float* q_b    = (const float*)d_in[4];
    const float* k_w    = (const float*)d_in[5];
    const float* v_w    = (const float*)d_in[6];
    const float* v_b    = (const float*)d_in[7];
    const float* out_w  = (const float*)d_in[8];
    const float* out_b  = (const float*)d_in[9];
    float* out = (float*)d_out;

    // 1. Prep: hidden hi/lo split + weight fp16 converts (one launch)
    {
        int nblk = (T_TOTAL * EMBED / 4 + 255) / 256;
        prep_kernel<<<dim3(nblk, 1, 5), 256>>>(hidden, q_w, k_w, v_w, out_w);
    }
    // 2. QKV GEMMs (1-pass, fused rope/split epilogues)
    cudaFuncSetAttribute(qkv_mma_kernel, cudaFuncAttributeMaxDynamicSharedMemorySize, SM_GEMM_TOTAL);
    qkv_mma_kernel<<<dim3(EMBED / 128, MTILES, 3), 256, SM_GEMM_TOTAL>>>(q_b, v_b, cosp, sinp);

    // 3. Flash attention (fp16 MMA, writes g_chi)
    cudaFuncSetAttribute(flash_kernel, cudaFuncAttributeMaxDynamicSharedMemorySize, FSM_TOTAL);
    flash_kernel<<<dim3(153, NHEADS), 128, FSM_TOTAL>>>();

    // 4. Output GEMM (1-pass, 3-stage, 2 CTAs/SM)
    cudaFuncSetAttribute(out_mma_kernel, cudaFuncAttributeMaxDynamicSharedMemorySize, SM_GEMM_TOTAL);
    out_mma_kernel<<<dim3(EMBED / 128, MTILES, 1), 256, SM_GEMM_TOTAL>>>(out_b, out);
}